// round 1
// baseline (speedup 1.0000x reference)
#include <cuda_runtime.h>

// Shift op: x[32,64,56,56] -> out[32,576,56,56]
// out[n, c*9 + s, y, x] = x[n, c, y + s/3 - 1, x + s%3 - 1], zero-padded.
//
// Pure memory-movement kernel. Output writes (231 MB) dominate DRAM traffic;
// input (25.7 MB) is L2-resident across the 9 rereads.
//
// One thread per float4 of output (aligned 128-bit stores), 4 guarded scalar
// loads per thread.

#define N_  32
#define C_  64
#define H_  56
#define W_  56
#define S_  9          // 3x3 shifts
#define W4 (W_ / 4)    // 14 float4 per row

__global__ __launch_bounds__(256) void shift_kernel(
    const float* __restrict__ in, float* __restrict__ out, int total_v4)
{
    int idx = blockIdx.x * blockDim.x + threadIdx.x;
    if (idx >= total_v4) return;

    // Decompose: idx -> (n, c, s, y, x4)
    int x4  = idx % W4;
    int t   = idx / W4;
    int y   = t % H_;
    t       = t / H_;
    int s   = t % S_;
    t       = t / S_;
    // t = n*C_ + c, which is exactly the input (n,c) plane index.
    int nc  = t;

    int dy = s / 3;        // 0,1,2
    int dx = s - dy * 3;   // 0,1,2

    int sy = y + dy - 1;

    float4 v;
    if ((unsigned)sy >= (unsigned)H_) {
        v = make_float4(0.f, 0.f, 0.f, 0.f);
    } else {
        const float* row = in + ((long long)nc * H_ + sy) * W_;
        int x0 = x4 * 4 + dx - 1;  // source x of first lane
        // guarded scalar loads (unaligned by dx-1); L2-resident input
        float a = ((unsigned)(x0 + 0) < (unsigned)W_) ? __ldg(row + x0 + 0) : 0.f;
        float b = ((unsigned)(x0 + 1) < (unsigned)W_) ? __ldg(row + x0 + 1) : 0.f;
        float c2 = ((unsigned)(x0 + 2) < (unsigned)W_) ? __ldg(row + x0 + 2) : 0.f;
        float d = ((unsigned)(x0 + 3) < (unsigned)W_) ? __ldg(row + x0 + 3) : 0.f;
        v = make_float4(a, b, c2, d);
    }

    reinterpret_cast<float4*>(out)[idx] = v;
}

extern "C" void kernel_launch(void* const* d_in, const int* in_sizes, int n_in,
                              void* d_out, int out_size) {
    const float* x = (const float*)d_in[0];
    float* out = (float*)d_out;
    int total_v4 = out_size / 4;   // 14,450,688
    int threads = 256;
    int blocks = (total_v4 + threads - 1) / threads;
    shift_kernel<<<blocks, threads>>>(x, out, total_v4);
}

// round 2
// speedup vs baseline: 1.4145x; 1.4145x over previous
#include <cuda_runtime.h>

// Shift op: x[32,64,56,56] -> out[32,576,56,56]
// out[n, c*9 + s, y, x] = x[n, c, y + s/3 - 1, x + s%3 - 1], zero-padded.
//
// R2: one thread per (nc, y, x4) producing all 9 shifted float4 outputs.
//  - 3 aligned float4 loads (rows y-1, y, y+1) + 6 edge scalars = 9 LDG
//    for 9 STG.128 (was 36 scalar LDG in R1).
//  - index decomposition once per 9 stores (was once per store).
//  - dx=0/1/2 variants built by register permutation of the loaded vector.

#define N_  32
#define C_  64
#define H_  56
#define W_  56
#define W4 (W_ / 4)    // 14 float4 per row

__global__ __launch_bounds__(256) void shift_kernel(
    const float* __restrict__ in, float* __restrict__ out, int total)
{
    int idx = blockIdx.x * blockDim.x + threadIdx.x;
    if (idx >= total) return;

    // idx -> (nc, y, x4)
    int x4 = idx % W4;
    int t  = idx / W4;
    int y  = t % H_;
    int nc = t / H_;

    int x0 = x4 * 4;
    const float* plane = in + (long long)nc * (H_ * W_);

    float4 v[3];
    float  lft[3], rgt[3];
    #pragma unroll
    for (int dy = 0; dy < 3; dy++) {
        int sy = y + dy - 1;
        if ((unsigned)sy < (unsigned)H_) {
            const float* row = plane + sy * W_;
            v[dy]   = *reinterpret_cast<const float4*>(row + x0);
            lft[dy] = (x0 > 0)       ? __ldg(row + x0 - 1) : 0.f;
            rgt[dy] = (x0 + 4 < W_)  ? __ldg(row + x0 + 4) : 0.f;
        } else {
            v[dy]   = make_float4(0.f, 0.f, 0.f, 0.f);
            lft[dy] = 0.f;
            rgt[dy] = 0.f;
        }
    }

    // out vector index for (nc, s, y, x4): ((nc*9 + s)*H + y)*W4 + x4
    float4* obase = reinterpret_cast<float4*>(out)
                    + ((long long)nc * 9) * (H_ * W4) + y * W4 + x4;
    const int sstride = H_ * W4;   // one s-plane in float4s

    #pragma unroll
    for (int dy = 0; dy < 3; dy++) {
        float4 b = v[dy];
        float4 a = make_float4(lft[dy], b.x, b.y, b.z);   // dx = 0 (shift left src)
        float4 c = make_float4(b.y, b.z, b.w, rgt[dy]);   // dx = 2
        obase[(dy * 3 + 0) * sstride] = a;
        obase[(dy * 3 + 1) * sstride] = b;
        obase[(dy * 3 + 2) * sstride] = c;
    }
}

extern "C" void kernel_launch(void* const* d_in, const int* in_sizes, int n_in,
                              void* d_out, int out_size) {
    const float* x = (const float*)d_in[0];
    float* out = (float*)d_out;
    int total = N_ * C_ * H_ * W4;   // 1,605,632 threads
    int threads = 256;
    int blocks = (total + threads - 1) / threads;
    shift_kernel<<<blocks, threads>>>(x, out, total);
}

// round 3
// speedup vs baseline: 1.4387x; 1.0171x over previous
#include <cuda_runtime.h>
#include <cstdint>

// Shift op: x[32,64,56,56] -> out[32,576,56,56]
// out[n, c*9 + s, y, x] = x[n, c, y + s/3 - 1, x + s%3 - 1], zero-padded.
//
// R3: stage output in SMEM (STS.128, ~4cyc issue) and drain to GMEM via
// cp.async.bulk.global.shared::cta (bulk-async engine), removing the
// 12-cyc/STG.128 LSU store cost that capped R2.
//
// Block = 128 threads, 112 active: (ty in 0..7) x (x4 in 0..13).
// Tile = 9 s-planes x 8 rows x 56 floats = 16128 B in SMEM, laid out
// [s][ty][x4] so each s-plane is 1792 contiguous bytes matching the
// output's (nc,s)-plane rows y0..y0+7 (contiguous in GMEM).

#define N_  32
#define C_  64
#define H_  56
#define W_  56
#define W4 (W_ / 4)      // 14
#define BY  8            // rows per block
#define NTILES_Y (H_ / BY)   // 7

__global__ __launch_bounds__(128) void shift_kernel(
    const float* __restrict__ in, float* __restrict__ out)
{
    __shared__ float4 tile[9 * BY * W4];   // 16128 B

    const int tid = threadIdx.x;
    const int nc    = blockIdx.x / NTILES_Y;
    const int ytile = blockIdx.x % NTILES_Y;
    const int y0    = ytile * BY;

    if (tid < BY * W4) {
        const int ty = tid / W4;
        const int x4 = tid % W4;
        const int y  = y0 + ty;
        const int x0 = x4 * 4;
        const float* plane = in + (long long)nc * (H_ * W_);

        float4 v[3];
        float  lft[3], rgt[3];
        #pragma unroll
        for (int dy = 0; dy < 3; dy++) {
            int sy = y + dy - 1;
            if ((unsigned)sy < (unsigned)H_) {
                const float* row = plane + sy * W_;
                v[dy]   = *reinterpret_cast<const float4*>(row + x0);
                lft[dy] = (x0 > 0)      ? __ldg(row + x0 - 1) : 0.f;
                rgt[dy] = (x0 + 4 < W_) ? __ldg(row + x0 + 4) : 0.f;
            } else {
                v[dy]   = make_float4(0.f, 0.f, 0.f, 0.f);
                lft[dy] = 0.f;
                rgt[dy] = 0.f;
            }
        }

        #pragma unroll
        for (int dy = 0; dy < 3; dy++) {
            float4 b = v[dy];
            float4 a = make_float4(lft[dy], b.x, b.y, b.z);   // dx = 0
            float4 c = make_float4(b.y, b.z, b.w, rgt[dy]);   // dx = 2
            tile[((dy * 3 + 0) * BY + ty) * W4 + x4] = a;
            tile[((dy * 3 + 1) * BY + ty) * W4 + x4] = b;
            tile[((dy * 3 + 2) * BY + ty) * W4 + x4] = c;
        }
    }

    __syncthreads();

    // Threads 0..8 each drain one s-plane (1792 contiguous bytes) via the
    // bulk-async engine.
    if (tid < 9) {
        const int s = tid;
        // order generic-proxy SMEM writes before async-proxy read
        asm volatile("fence.proxy.async.shared::cta;" ::: "memory");

        uint32_t saddr = (uint32_t)__cvta_generic_to_shared(
            reinterpret_cast<const char*>(tile) + s * (BY * W_ * 4));
        const float* gdst = out + ((long long)(nc * 9 + s) * H_ + y0) * W_;

        asm volatile(
            "cp.async.bulk.global.shared::cta.bulk_group [%0], [%1], %2;"
            :: "l"(gdst), "r"(saddr), "r"(BY * W_ * 4)
            : "memory");
        asm volatile("cp.async.bulk.commit_group;" ::: "memory");
        asm volatile("cp.async.bulk.wait_group 0;" ::: "memory");
    }
}

extern "C" void kernel_launch(void* const* d_in, const int* in_sizes, int n_in,
                              void* d_out, int out_size) {
    const float* x = (const float*)d_in[0];
    float* out = (float*)d_out;
    int blocks = N_ * C_ * NTILES_Y;   // 2048 * 7 = 14336
    shift_kernel<<<blocks, 128>>>(x, out);
}

// round 4
// speedup vs baseline: 1.5706x; 1.0917x over previous
#include <cuda_runtime.h>

// Shift op: x[32,64,56,56] -> out[32,576,56,56]
// out[n, c*9 + s, y, x] = x[n, c, y + s/3 - 1, x + s%3 - 1], zero-padded.
//
// R4: direct STG (no smem/barrier tail), 2 output rows per thread:
//  - 18 independent STG.128 per thread (2x the in-flight stores of R2),
//  - 4 aligned float4 loads + 8 edge scalars for 18 stores,
//  - __stcs on stores (output never re-read; keep L2 for the 9x-reused input).

#define N_  32
#define C_  64
#define H_  56
#define W_  56
#define W4 (W_ / 4)      // 14
#define H2 (H_ / 2)      // 28 row-pairs

__global__ __launch_bounds__(256) void shift_kernel(
    const float* __restrict__ in, float* __restrict__ out, int total)
{
    int idx = blockIdx.x * blockDim.x + threadIdx.x;
    if (idx >= total) return;

    // idx -> (nc, y2, x4);  y = 2*y2
    int x4 = idx % W4;
    int t  = idx / W4;
    int y2 = t % H2;
    int nc = t / H2;
    int y  = y2 * 2;

    int x0 = x4 * 4;
    const float* plane = in + (long long)nc * (H_ * W_);

    // rows y-1 .. y+2
    float4 v[4];
    float  lft[4], rgt[4];
    #pragma unroll
    for (int r = 0; r < 4; r++) {
        int sy = y + r - 1;
        if ((unsigned)sy < (unsigned)H_) {
            const float* row = plane + sy * W_;
            v[r]   = *reinterpret_cast<const float4*>(row + x0);
            lft[r] = (x0 > 0)      ? __ldg(row + x0 - 1) : 0.f;
            rgt[r] = (x0 + 4 < W_) ? __ldg(row + x0 + 4) : 0.f;
        } else {
            v[r]   = make_float4(0.f, 0.f, 0.f, 0.f);
            lft[r] = 0.f;
            rgt[r] = 0.f;
        }
    }

    // out float4 base for (nc, s=0, y, x4)
    float4* obase = reinterpret_cast<float4*>(out)
                    + ((long long)nc * 9) * (H_ * W4) + y * W4 + x4;
    const int sstride = H_ * W4;   // one s-plane in float4s

    #pragma unroll
    for (int dy = 0; dy < 3; dy++) {
        #pragma unroll
        for (int r = 0; r < 2; r++) {
            float4 b = v[dy + r];                              // src row y+r+dy-1
            float4 a = make_float4(lft[dy + r], b.x, b.y, b.z); // dx = 0
            float4 c = make_float4(b.y, b.z, b.w, rgt[dy + r]); // dx = 2
            float4* o = obase + r * W4;
            __stcs(o + (dy * 3 + 0) * sstride, a);
            __stcs(o + (dy * 3 + 1) * sstride, b);
            __stcs(o + (dy * 3 + 2) * sstride, c);
        }
    }
}

extern "C" void kernel_launch(void* const* d_in, const int* in_sizes, int n_in,
                              void* d_out, int out_size) {
    const float* x = (const float*)d_in[0];
    float* out = (float*)d_out;
    int total = N_ * C_ * H2 * W4;   // 802,816 threads
    int threads = 256;
    int blocks = (total + threads - 1) / threads;
    shift_kernel<<<blocks, threads>>>(x, out, total);
}

// round 7
// speedup vs baseline: 1.5732x; 1.0016x over previous
#include <cuda_runtime.h>
#include <cstdint>

// Shift op: x[32,64,56,56] -> out[32,576,56,56]
// out[n, c*9 + s, y, x] = x[n, c, y + s/3 - 1, x + s%3 - 1], zero-padded.
//
// R6 = R4 (2 output rows/thread, 18 STG.128) + L2 residency control via
// createpolicy/cache_hint (ptxas rejects bare .L2::evict_last on <256-bit ld):
//  - loads:  ld.global.nc.L2::cache_hint with fractional evict_last policy
//            -> pin the 26MB input in L2 across its 9 rereads.
//  - stores: st.global.cs (evict-first) -> write stream doesn't churn L2.

#define N_  32
#define C_  64
#define H_  56
#define W_  56
#define W4 (W_ / 4)      // 14
#define H2 (H_ / 2)      // 28 row-pairs

__device__ __forceinline__ uint64_t mk_policy() {
    uint64_t p;
    asm("createpolicy.fractional.L2::evict_last.b64 %0, 1.0;" : "=l"(p));
    return p;
}

__device__ __forceinline__ float4 ldg_el4(const float* p, uint64_t pol) {
    float4 v;
    asm volatile("ld.global.nc.L2::cache_hint.v4.f32 {%0,%1,%2,%3}, [%4], %5;"
                 : "=f"(v.x), "=f"(v.y), "=f"(v.z), "=f"(v.w)
                 : "l"(p), "l"(pol));
    return v;
}
__device__ __forceinline__ float ldg_el1(const float* p, uint64_t pol) {
    float v;
    asm volatile("ld.global.nc.L2::cache_hint.f32 %0, [%1], %2;"
                 : "=f"(v) : "l"(p), "l"(pol));
    return v;
}

__global__ __launch_bounds__(256) void shift_kernel(
    const float* __restrict__ in, float* __restrict__ out, int total)
{
    int idx = blockIdx.x * blockDim.x + threadIdx.x;
    if (idx >= total) return;

    const uint64_t pol = mk_policy();

    // idx -> (nc, y2, x4);  y = 2*y2
    int x4 = idx % W4;
    int t  = idx / W4;
    int y2 = t % H2;
    int nc = t / H2;
    int y  = y2 * 2;

    int x0 = x4 * 4;
    const float* plane = in + (long long)nc * (H_ * W_);

    // rows y-1 .. y+2
    float4 v[4];
    float  lft[4], rgt[4];
    #pragma unroll
    for (int r = 0; r < 4; r++) {
        int sy = y + r - 1;
        if ((unsigned)sy < (unsigned)H_) {
            const float* row = plane + sy * W_;
            v[r]   = ldg_el4(row + x0, pol);
            lft[r] = (x0 > 0)      ? ldg_el1(row + x0 - 1, pol) : 0.f;
            rgt[r] = (x0 + 4 < W_) ? ldg_el1(row + x0 + 4, pol) : 0.f;
        } else {
            v[r]   = make_float4(0.f, 0.f, 0.f, 0.f);
            lft[r] = 0.f;
            rgt[r] = 0.f;
        }
    }

    // out float4 base for (nc, s=0, y, x4)
    float4* obase = reinterpret_cast<float4*>(out)
                    + ((long long)nc * 9) * (H_ * W4) + y * W4 + x4;
    const int sstride = H_ * W4;   // one s-plane in float4s

    #pragma unroll
    for (int dy = 0; dy < 3; dy++) {
        #pragma unroll
        for (int r = 0; r < 2; r++) {
            float4 b = v[dy + r];                               // src row y+r+dy-1
            float4 a = make_float4(lft[dy + r], b.x, b.y, b.z); // dx = 0
            float4 c = make_float4(b.y, b.z, b.w, rgt[dy + r]); // dx = 2
            float4* o = obase + r * W4;
            __stcs(o + (dy * 3 + 0) * sstride, a);
            __stcs(o + (dy * 3 + 1) * sstride, b);
            __stcs(o + (dy * 3 + 2) * sstride, c);
        }
    }
}

extern "C" void kernel_launch(void* const* d_in, const int* in_sizes, int n_in,
                              void* d_out, int out_size) {
    const float* x = (const float*)d_in[0];
    float* out = (float*)d_out;
    int total = N_ * C_ * H2 * W4;   // 802,816 threads
    int threads = 256;
    int blocks = (total + threads - 1) / threads;
    shift_kernel<<<blocks, threads>>>(x, out, total);
}